// round 10
// baseline (speedup 1.0000x reference)
#include <cuda_runtime.h>
#include <cuda_bf16.h>
#include <math.h>

// Problem constants (fixed by the dataset)
#define N_NODES  100000
#define N_EDGES  1600000
#define N_FEAT   512
#define HIDDEN   128
#define N_CLASS  40

#define SCAN_BLK   1024
#define SCAN_NBLK  ((N_NODES + SCAN_BLK - 1) / SCAN_BLK)   // 98

// ---------------- scratch (device globals; no cudaMalloc allowed) ------------
__device__ __align__(16) int      g_cnt   [N_NODES];
__device__ __align__(16) float    g_dinv  [N_NODES];
__device__ __align__(16) int      g_rowptr[N_NODES + 1];
__device__ __align__(16) int      g_pos   [N_NODES];
__device__ __align__(16) int      g_bsum  [SCAN_NBLK];
__device__ __align__(16) int      g_csrc  [N_EDGES];
__device__ __align__(16) unsigned g_hp  [(size_t)N_NODES * (HIDDEN / 2)];   // x@W1, bf16x2
__device__ __align__(16) unsigned g_a1p [(size_t)N_NODES * (HIDDEN / 2)];   // relu(agg1+b1), bf16x2
__device__ __align__(16) unsigned g_h2p [(size_t)N_NODES * (N_CLASS / 2)];  // dinv*(a1'@W2), bf16x2
__device__ int g_is64;

// ---------------- small helpers ----------------------------------------------
__device__ __forceinline__ void cp16(void* smem, const void* g, int sz) {
    unsigned sa = (unsigned)__cvta_generic_to_shared(smem);
    asm volatile("cp.async.cg.shared.global [%0], [%1], 16, %2;" :: "r"(sa), "l"(g), "r"(sz));
}
__device__ __forceinline__ void cp_commit() { asm volatile("cp.async.commit_group;"); }

__device__ __forceinline__ unsigned pack_bf16(float lo, float hi) {
    __nv_bfloat162 t = __float22bfloat162_rn(make_float2(lo, hi));
    return *reinterpret_cast<unsigned*>(&t);
}
__device__ __forceinline__ float2 unpack_bf16(unsigned u) {
    __nv_bfloat162 t = *reinterpret_cast<__nv_bfloat162*>(&u);
    return __bfloat1622float2(t);
}

// ---------------- init: detect dtype + zero counters ---------------------------
__global__ void k_init(const unsigned* __restrict__ ei_u32) {
    int i = blockIdx.x * blockDim.x + threadIdx.x;
    if (i < N_NODES) g_cnt[i] = 0;
    if (i == 0) {
        int all_zero = 1;
        #pragma unroll
        for (int j = 0; j < 8; j++)
            if (ei_u32[2 * j + 1] != 0u) all_zero = 0;
        g_is64 = all_zero;
    }
}

// count in-degree: 4 edges/thread, vectorized dst loads
__global__ void k_count(const void* __restrict__ ei_raw) {
    int e = (blockIdx.x * blockDim.x + threadIdx.x) * 4;
    if (e >= N_EDGES) return;
    int d0, d1, d2, d3;
    if (g_is64) {
        const longlong2* p = (const longlong2*)((const long long*)ei_raw + N_EDGES + e);
        longlong2 a = p[0], b = p[1];
        d0 = (int)a.x; d1 = (int)a.y; d2 = (int)b.x; d3 = (int)b.y;
    } else {
        int4 v = *(const int4*)((const int*)ei_raw + N_EDGES + e);
        d0 = v.x; d1 = v.y; d2 = v.z; d3 = v.w;
    }
    atomicAdd(&g_cnt[d0], 1);
    atomicAdd(&g_cnt[d1], 1);
    atomicAdd(&g_cnt[d2], 1);
    atomicAdd(&g_cnt[d3], 1);
}

// ---------------- scan pass 1: per-1024-block exclusive prefix + block total ---
// (also emits dinv, fused)
__global__ __launch_bounds__(256) void k_scan1() {
    __shared__ int wsum[8];
    int bid = blockIdx.x, tid = threadIdx.x;
    int lane = tid & 31, wid = tid >> 5;
    int base = bid * SCAN_BLK + tid * 4;

    int v[4];
    #pragma unroll
    for (int i = 0; i < 4; i++) {
        int idx = base + i;
        v[i] = (idx < N_NODES) ? g_cnt[idx] : 0;
        if (idx < N_NODES) g_dinv[idx] = rsqrtf((float)v[i] + 1.0f);
    }
    int t1 = v[0] + v[1];
    int t2 = t1 + v[2];
    int tot = t2 + v[3];

    int x = tot;
    #pragma unroll
    for (int o = 1; o < 32; o <<= 1) {
        int y = __shfl_up_sync(0xFFFFFFFFu, x, o);
        if (lane >= o) x += y;
    }
    if (lane == 31) wsum[wid] = x;
    __syncthreads();
    if (wid == 0) {
        int w = (lane < 8) ? wsum[lane] : 0;
        #pragma unroll
        for (int o = 1; o < 8; o <<= 1) {
            int y = __shfl_up_sync(0xFFFFFFFFu, w, o);
            if (lane >= o) w += y;
        }
        if (lane < 8) wsum[lane] = w;
        if (lane == 7) g_bsum[bid] = w;
    }
    __syncthreads();

    int thread_excl = x - tot + (wid > 0 ? wsum[wid - 1] : 0);
    int p[4] = {thread_excl, thread_excl + v[0], thread_excl + t1, thread_excl + t2};
    #pragma unroll
    for (int i = 0; i < 4; i++) {
        int idx = base + i;
        if (idx < N_NODES) g_rowptr[idx] = p[i];
    }
}

// scan pass 2 (fused former scan2+scan3): each 256-wide block redundantly
// reduces the g_bsum prefix for its (single) 1024-block, then finalizes rowptr.
__global__ __launch_bounds__(256) void k_scan3() {
    __shared__ int s_off;
    int base = blockIdx.x * 256;
    int blk = base >> 10;          // all 256 indices share one scan-block id
    if (threadIdx.x < 32) {
        int s = 0;
        for (int j = threadIdx.x; j < blk; j += 32) s += g_bsum[j];
        #pragma unroll
        for (int o = 16; o > 0; o >>= 1) s += __shfl_xor_sync(0xFFFFFFFFu, s, o);
        if (threadIdx.x == 0) s_off = s;
    }
    __syncthreads();
    int i = base + threadIdx.x;
    if (i < N_NODES) {
        int r = g_rowptr[i] + s_off;
        g_rowptr[i] = r;
        g_pos[i] = r;
    }
    if (blockIdx.x == 0 && threadIdx.x == 0) g_rowptr[N_NODES] = N_EDGES;
}

// fill CSR: src index only; 2 edges/thread, vectorized loads
__global__ void k_scatter(const void* __restrict__ ei_raw) {
    int e = (blockIdx.x * blockDim.x + threadIdx.x) * 2;
    if (e >= N_EDGES) return;
    int s0, s1, d0, d1;
    if (g_is64) {
        longlong2 sv = *(const longlong2*)((const long long*)ei_raw + e);
        longlong2 dv = *(const longlong2*)((const long long*)ei_raw + N_EDGES + e);
        s0 = (int)sv.x; s1 = (int)sv.y; d0 = (int)dv.x; d1 = (int)dv.y;
    } else {
        int2 sv = *(const int2*)((const int*)ei_raw + e);
        int2 dv = *(const int2*)((const int*)ei_raw + N_EDGES + e);
        s0 = sv.x; s1 = sv.y; d0 = dv.x; d1 = dv.y;
    }
    int p0 = atomicAdd(&g_pos[d0], 1);
    g_csrc[p0] = s0;
    int p1 = atomicAdd(&g_pos[d1], 1);
    g_csrc[p1] = s1;
}

// ---------------- GEMM1 (tf32 mma + cp.async double buffer) -------------------
#define BM 128
#define BK 32
#define A_PAD 36
#define B_PAD 132
#define G1_SMEM ((2 * BM * A_PAD + 2 * BK * B_PAD) * 4)   // 70656 bytes

__device__ __forceinline__ void mma_tf32(float c[4], const unsigned a[4], const unsigned b[2]) {
    asm volatile(
        "mma.sync.aligned.m16n8k8.row.col.f32.tf32.tf32.f32 "
        "{%0,%1,%2,%3}, {%4,%5,%6,%7}, {%8,%9}, {%0,%1,%2,%3};"
        : "+f"(c[0]), "+f"(c[1]), "+f"(c[2]), "+f"(c[3])
        : "r"(a[0]), "r"(a[1]), "r"(a[2]), "r"(a[3]), "r"(b[0]), "r"(b[1]));
}

__global__ __launch_bounds__(256, 2) void k_gemm1_tc(const float* __restrict__ X,
                                                     const float* __restrict__ W) {
    extern __shared__ unsigned dynsmem[];
    unsigned* Asm = dynsmem;                      // [2][BM][A_PAD]
    unsigned* Bsm = dynsmem + 2 * BM * A_PAD;     // [2][BK][B_PAD]
    #define AS(b, m, k) Asm[(b) * BM * A_PAD + (m) * A_PAD + (k)]
    #define BS(b, k, n) Bsm[(b) * BK * B_PAD + (k) * B_PAD + (n)]

    const int tid = threadIdx.x;
    const int wid = tid >> 5;
    const int lane = tid & 31;
    const int g  = lane >> 2;
    const int tg = lane & 3;
    const int wm = wid >> 2;
    const int wn = wid & 3;
    const int mBase = wm * 64;
    const int nBase = wn * 32;
    const int rowBase = blockIdx.x * BM;

    float c[4][4][4];
    #pragma unroll
    for (int mi = 0; mi < 4; mi++)
        #pragma unroll
        for (int ni = 0; ni < 4; ni++)
            #pragma unroll
            for (int r = 0; r < 4; r++) c[mi][ni][r] = 0.0f;

    auto load_tiles = [&](int buf, int k0) {
        #pragma unroll
        for (int i = 0; i < 4; i++) {
            int slot = tid + i * 256;
            int m  = slot >> 3;
            int kq = slot & 7;
            int gr = rowBase + m;
            int valid = (gr < N_NODES);
            const float* src = X + (size_t)(valid ? gr : 0) * N_FEAT + k0 + kq * 4;
            cp16(&AS(buf, m, kq * 4), src, valid ? 16 : 0);
        }
        #pragma unroll
        for (int i = 0; i < 4; i++) {
            int slot = tid + i * 256;
            int kk = slot >> 5;
            int nq = slot & 31;
            cp16(&BS(buf, kk, nq * 4), W + (size_t)(k0 + kk) * HIDDEN + nq * 4, 16);
        }
        cp_commit();
    };

    load_tiles(0, 0);

    const int NIT = N_FEAT / BK;   // 16
    for (int it = 0; it < NIT; it++) {
        int cur = it & 1;
        if (it < NIT - 1) load_tiles(cur ^ 1, (it + 1) * BK);
        if (it < NIT - 1) { asm volatile("cp.async.wait_group 1;" ::: "memory"); }
        else              { asm volatile("cp.async.wait_group 0;" ::: "memory"); }
        __syncthreads();

        #pragma unroll
        for (int ks = 0; ks < 4; ks++) {
            const int kb = ks * 8;
            unsigned a[4][4];
            #pragma unroll
            for (int mi = 0; mi < 4; mi++) {
                int r0 = mBase + mi * 16 + g;
                a[mi][0] = AS(cur, r0,     kb + tg);
                a[mi][1] = AS(cur, r0 + 8, kb + tg);
                a[mi][2] = AS(cur, r0,     kb + tg + 4);
                a[mi][3] = AS(cur, r0 + 8, kb + tg + 4);
            }
            unsigned b[4][2];
            #pragma unroll
            for (int ni = 0; ni < 4; ni++) {
                int col = nBase + ni * 8 + g;
                b[ni][0] = BS(cur, kb + tg,     col);
                b[ni][1] = BS(cur, kb + tg + 4, col);
            }
            #pragma unroll
            for (int mi = 0; mi < 4; mi++)
                #pragma unroll
                for (int ni = 0; ni < 4; ni++)
                    mma_tf32(c[mi][ni], a[mi], b[ni]);
        }
        __syncthreads();
    }

    #pragma unroll
    for (int mi = 0; mi < 4; mi++) {
        int r0 = rowBase + mBase + mi * 16 + g;
        #pragma unroll
        for (int ni = 0; ni < 4; ni++) {
            int colu = (nBase + ni * 8) / 2 + tg;
            if (r0 < N_NODES)
                g_hp[(size_t)r0 * 64 + colu] = pack_bf16(c[mi][ni][0], c[mi][ni][1]);
            if (r0 + 8 < N_NODES)
                g_hp[(size_t)(r0 + 8) * 64 + colu] = pack_bf16(c[mi][ni][2], c[mi][ni][3]);
        }
    }
    #undef AS
    #undef BS
}

// ---------------- agg1: CSR gather, weight = dinv[s]; final *dinv[n] ----------
__global__ __launch_bounds__(256) void k_agg1_g(const float* __restrict__ b1) {
    int t = blockIdx.x * blockDim.x + threadIdx.x;
    int n = t >> 5;
    if (n >= N_NODES) return;
    int lane = t & 31;

    float wn = g_dinv[n];

    uint2 su = *(const uint2*)&g_hp[(size_t)n * 64 + 2 * lane];
    float2 s0 = unpack_bf16(su.x), s1 = unpack_bf16(su.y);
    float4 acc = make_float4(s0.x * wn, s0.y * wn, s1.x * wn, s1.y * wn);

    int e   = g_rowptr[n];
    int end = g_rowptr[n + 1];

    for (; e + 4 <= end; e += 4) {
        int i0 = g_csrc[e], i1 = g_csrc[e + 1], i2 = g_csrc[e + 2], i3 = g_csrc[e + 3];
        float w0 = g_dinv[i0], w1 = g_dinv[i1], w2 = g_dinv[i2], w3 = g_dinv[i3];
        uint2 u0 = *(const uint2*)&g_hp[(size_t)i0 * 64 + 2 * lane];
        uint2 u1 = *(const uint2*)&g_hp[(size_t)i1 * 64 + 2 * lane];
        uint2 u2 = *(const uint2*)&g_hp[(size_t)i2 * 64 + 2 * lane];
        uint2 u3 = *(const uint2*)&g_hp[(size_t)i3 * 64 + 2 * lane];
        float2 a, b;
        a = unpack_bf16(u0.x); b = unpack_bf16(u0.y);
        acc.x = fmaf(a.x, w0, acc.x); acc.y = fmaf(a.y, w0, acc.y);
        acc.z = fmaf(b.x, w0, acc.z); acc.w = fmaf(b.y, w0, acc.w);
        a = unpack_bf16(u1.x); b = unpack_bf16(u1.y);
        acc.x = fmaf(a.x, w1, acc.x); acc.y = fmaf(a.y, w1, acc.y);
        acc.z = fmaf(b.x, w1, acc.z); acc.w = fmaf(b.y, w1, acc.w);
        a = unpack_bf16(u2.x); b = unpack_bf16(u2.y);
        acc.x = fmaf(a.x, w2, acc.x); acc.y = fmaf(a.y, w2, acc.y);
        acc.z = fmaf(b.x, w2, acc.z); acc.w = fmaf(b.y, w2, acc.w);
        a = unpack_bf16(u3.x); b = unpack_bf16(u3.y);
        acc.x = fmaf(a.x, w3, acc.x); acc.y = fmaf(a.y, w3, acc.y);
        acc.z = fmaf(b.x, w3, acc.z); acc.w = fmaf(b.y, w3, acc.w);
    }
    for (; e < end; e++) {
        int i0 = g_csrc[e];
        float w0 = g_dinv[i0];
        uint2 u0 = *(const uint2*)&g_hp[(size_t)i0 * 64 + 2 * lane];
        float2 a = unpack_bf16(u0.x), b = unpack_bf16(u0.y);
        acc.x = fmaf(a.x, w0, acc.x); acc.y = fmaf(a.y, w0, acc.y);
        acc.z = fmaf(b.x, w0, acc.z); acc.w = fmaf(b.y, w0, acc.w);
    }

    float4 bv = *(const float4*)&b1[lane * 4];
    acc.x = fmaxf(fmaf(acc.x, wn, bv.x), 0.0f);
    acc.y = fmaxf(fmaf(acc.y, wn, bv.y), 0.0f);
    acc.z = fmaxf(fmaf(acc.z, wn, bv.z), 0.0f);
    acc.w = fmaxf(fmaf(acc.w, wn, bv.w), 0.0f);

    uint2 o;
    o.x = pack_bf16(acc.x, acc.y);
    o.y = pack_bf16(acc.z, acc.w);
    *(uint2*)&g_a1p[(size_t)n * 64 + 2 * lane] = o;
}

// ---------------- GEMM2 (bf16 mma): g_h2p = dinv * (a1' @ W2) ------------------
#define A2_PAD 68
__global__ __launch_bounds__(256) void k_gemm2_tc(const float* __restrict__ W2) {
    __shared__ unsigned sAp[128][A2_PAD];
    __shared__ unsigned sBp[64][N_CLASS];

    const int tid = threadIdx.x;
    const int wid = tid >> 5;
    const int lane = tid & 31;
    const int g  = lane >> 2;
    const int tg = lane & 3;
    const int rowBase = blockIdx.x * 128;

    for (int i = tid; i < 64 * N_CLASS; i += 256) {
        int k2 = i / N_CLASS, n = i % N_CLASS;
        float lo = W2[(size_t)(2 * k2) * N_CLASS + n];
        float hi = W2[(size_t)(2 * k2 + 1) * N_CLASS + n];
        sBp[k2][n] = pack_bf16(lo, hi);
    }
    #pragma unroll
    for (int i = 0; i < 8; i++) {
        int slot = tid + i * 256;
        int m = slot >> 4;
        int j = slot & 15;
        int gr = rowBase + m;
        int valid = (gr < N_NODES);
        cp16(&sAp[m][j * 4], g_a1p + (size_t)(valid ? gr : 0) * 64 + j * 4, valid ? 16 : 0);
    }
    cp_commit();
    asm volatile("cp.async.wait_group 0;" ::: "memory");
    __syncthreads();

    const int mBase = wid * 16;
    float c[5][4];
    #pragma unroll
    for (int ni = 0; ni < 5; ni++)
        #pragma unroll
        for (int r = 0; r < 4; r++) c[ni][r] = 0.0f;

    #pragma unroll
    for (int ks = 0; ks < 8; ks++) {
        int k2b = ks * 8;
        int r0 = mBase + g;
        unsigned a0 = sAp[r0    ][k2b + tg];
        unsigned a1 = sAp[r0 + 8][k2b + tg];
        unsigned a2 = sAp[r0    ][k2b + tg + 4];
        unsigned a3 = sAp[r0 + 8][k2b + tg + 4];
        #pragma unroll
        for (int ni = 0; ni < 5; ni++) {
            unsigned b0 = sBp[k2b + tg    ][ni * 8 + g];
            unsigned b1r = sBp[k2b + tg + 4][ni * 8 + g];
            asm volatile(
                "mma.sync.aligned.m16n8k16.row.col.f32.bf16.bf16.f32 "
                "{%0,%1,%2,%3}, {%4,%5,%6,%7}, {%8,%9}, {%0,%1,%2,%3};"
                : "+f"(c[ni][0]), "+f"(c[ni][1]), "+f"(c[ni][2]), "+f"(c[ni][3])
                : "r"(a0), "r"(a1), "r"(a2), "r"(a3), "r"(b0), "r"(b1r));
        }
    }

    int r0 = rowBase + mBase + g;
    float w0 = (r0 < N_NODES) ? g_dinv[r0] : 0.0f;
    float w1 = (r0 + 8 < N_NODES) ? g_dinv[r0 + 8] : 0.0f;
    #pragma unroll
    for (int ni = 0; ni < 5; ni++) {
        int colu = ni * 4 + tg;
        if (r0 < N_NODES)
            g_h2p[(size_t)r0 * 20 + colu] = pack_bf16(c[ni][0] * w0, c[ni][1] * w0);
        if (r0 + 8 < N_NODES)
            g_h2p[(size_t)(r0 + 8) * 20 + colu] = pack_bf16(c[ni][2] * w1, c[ni][3] * w1);
    }
}

// ---------------- fused agg2 + log_softmax: warp per node ---------------------
// Lane l<20 owns classes {2l, 2l+1}. Gathers pre-scaled h2' rows, scales by
// dinv[n], adds b2, then warp-reduced log-softmax, writes fp32 out.
__global__ __launch_bounds__(256) void k_agg2lsm(const float* __restrict__ b2,
                                                 float* __restrict__ out) {
    int n = blockIdx.x * 8 + (threadIdx.x >> 5);
    if (n >= N_NODES) return;
    int lane = threadIdx.x & 31;
    bool active = lane < 20;

    float wn = g_dinv[n];
    float2 acc = make_float2(0.0f, 0.0f);
    if (active) acc = unpack_bf16(g_h2p[(size_t)n * 20 + lane]);

    int e   = g_rowptr[n];
    int end = g_rowptr[n + 1];
    for (; e + 2 <= end; e += 2) {
        int i0 = g_csrc[e], i1 = g_csrc[e + 1];
        if (active) {
            float2 v0 = unpack_bf16(g_h2p[(size_t)i0 * 20 + lane]);
            float2 v1 = unpack_bf16(g_h2p[(size_t)i1 * 20 + lane]);
            acc.x += v0.x + v1.x;
            acc.y += v0.y + v1.y;
        }
    }
    if (e < end) {
        int i0 = g_csrc[e];
        if (active) {
            float2 v0 = unpack_bf16(g_h2p[(size_t)i0 * 20 + lane]);
            acc.x += v0.x;
            acc.y += v0.y;
        }
    }

    float x0 = -1e30f, x1 = -1e30f;
    if (active) {
        float2 bb = *(const float2*)&b2[2 * lane];
        x0 = fmaf(acc.x, wn, bb.x);
        x1 = fmaf(acc.y, wn, bb.y);
    }

    float m = fmaxf(x0, x1);
    #pragma unroll
    for (int o = 16; o > 0; o >>= 1) m = fmaxf(m, __shfl_xor_sync(0xFFFFFFFFu, m, o));

    float s = active ? (expf(x0 - m) + expf(x1 - m)) : 0.0f;
    #pragma unroll
    for (int o = 16; o > 0; o >>= 1) s += __shfl_xor_sync(0xFFFFFFFFu, s, o);

    float ls = m + logf(s);
    if (active)
        *(float2*)&out[(size_t)n * N_CLASS + 2 * lane] = make_float2(x0 - ls, x1 - ls);
}

// ---------------- launcher: fork-join (prep || gemm1) --------------------------
extern "C" void kernel_launch(void* const* d_in, const int* in_sizes, int n_in,
                              void* d_out, int out_size) {
    const float* x  = (const float*)d_in[0];
    const void*  ei = d_in[1];
    const float* W1 = (const float*)d_in[2];
    const float* b1 = (const float*)d_in[3];
    const float* W2 = (const float*)d_in[4];
    const float* b2 = (const float*)d_in[5];
    float* out = (float*)d_out;

    static cudaStream_t s_prep = nullptr;
    static cudaEvent_t ev_fork = nullptr, ev_join = nullptr;
    if (s_prep == nullptr) {
        cudaStreamCreateWithFlags(&s_prep, cudaStreamNonBlocking);
        cudaEventCreateWithFlags(&ev_fork, cudaEventDisableTiming);
        cudaEventCreateWithFlags(&ev_join, cudaEventDisableTiming);
        cudaFuncSetAttribute(k_gemm1_tc, cudaFuncAttributeMaxDynamicSharedMemorySize, G1_SMEM);
    }

    // fork: prep chain on side stream, gemm1 on main stream
    cudaEventRecord(ev_fork, 0);
    cudaStreamWaitEvent(s_prep, ev_fork, 0);

    k_init<<<(N_NODES + 255) / 256, 256, 0, s_prep>>>((const unsigned*)ei);
    k_count<<<(N_EDGES / 4 + 255) / 256, 256, 0, s_prep>>>(ei);
    k_scan1<<<SCAN_NBLK, 256, 0, s_prep>>>();
    k_scan3<<<(N_NODES + 255) / 256, 256, 0, s_prep>>>();
    k_scatter<<<(N_EDGES / 2 + 255) / 256, 256, 0, s_prep>>>(ei);

    k_gemm1_tc<<<(N_NODES + BM - 1) / BM, 256, G1_SMEM>>>(x, W1);

    // join
    cudaEventRecord(ev_join, s_prep);
    cudaStreamWaitEvent(0, ev_join, 0);

    k_agg1_g<<<(N_NODES * 32 + 255) / 256, 256>>>(b1);
    k_gemm2_tc<<<(N_NODES + 127) / 128, 256>>>(W2);
    k_agg2lsm<<<(N_NODES + 7) / 8, 256>>>(b2, out);
}

// round 12
// speedup vs baseline: 1.0016x; 1.0016x over previous
#include <cuda_runtime.h>
#include <cuda_bf16.h>
#include <math.h>

// Problem constants (fixed by the dataset)
#define N_NODES  100000
#define N_EDGES  1600000
#define N_FEAT   512
#define HIDDEN   128
#define N_CLASS  40

#define SCAN_BLK   1024
#define SCAN_NBLK  ((N_NODES + SCAN_BLK - 1) / SCAN_BLK)   // 98

// ---------------- scratch (device globals; no cudaMalloc allowed) ------------
__device__ __align__(16) int      g_cnt   [N_NODES];
__device__ __align__(16) float    g_dinv  [N_NODES];
__device__ __align__(16) int      g_rowptr[N_NODES + 1];
__device__ __align__(16) int      g_pos   [N_NODES];
__device__ __align__(16) int      g_bsum  [SCAN_NBLK];
__device__ __align__(16) int      g_csrc  [N_EDGES];
__device__ __align__(16) unsigned g_hp  [(size_t)N_NODES * (HIDDEN / 2)];   // x@W1, bf16x2
__device__ __align__(16) unsigned g_a1p [(size_t)N_NODES * (HIDDEN / 2)];   // relu(agg1+b1), bf16x2
__device__ __align__(16) unsigned g_h2p [(size_t)N_NODES * (N_CLASS / 2)];  // dinv*(a1'@W2), bf16x2
__device__ int g_is64;

// ---------------- small helpers ----------------------------------------------
__device__ __forceinline__ void cp16(void* smem, const void* g, int sz) {
    unsigned sa = (unsigned)__cvta_generic_to_shared(smem);
    asm volatile("cp.async.cg.shared.global [%0], [%1], 16, %2;" :: "r"(sa), "l"(g), "r"(sz));
}
__device__ __forceinline__ void cp_commit() { asm volatile("cp.async.commit_group;"); }

__device__ __forceinline__ unsigned pack_bf16(float lo, float hi) {
    __nv_bfloat162 t = __float22bfloat162_rn(make_float2(lo, hi));
    return *reinterpret_cast<unsigned*>(&t);
}
__device__ __forceinline__ float2 unpack_bf16(unsigned u) {
    __nv_bfloat162 t = *reinterpret_cast<__nv_bfloat162*>(&u);
    return __bfloat1622float2(t);
}

// ---------------- init: detect dtype + zero counters ---------------------------
__global__ void k_init(const unsigned* __restrict__ ei_u32) {
    int i = blockIdx.x * blockDim.x + threadIdx.x;
    if (i < N_NODES) g_cnt[i] = 0;
    if (i == 0) {
        int all_zero = 1;
        #pragma unroll
        for (int j = 0; j < 8; j++)
            if (ei_u32[2 * j + 1] != 0u) all_zero = 0;
        g_is64 = all_zero;
    }
}

__device__ __forceinline__ void load_edge(const void* ei_raw, int e, int& s, int& d) {
    if (g_is64) {
        const long long* ei = (const long long*)ei_raw;
        s = (int)ei[e];
        d = (int)ei[N_EDGES + e];
    } else {
        const int* ei = (const int*)ei_raw;
        s = ei[e];
        d = ei[N_EDGES + e];
    }
}

// count in-degree: 1 edge/thread (max atomic MLP — vectorized variant regressed)
__global__ void k_count(const void* __restrict__ ei_raw) {
    int e = blockIdx.x * blockDim.x + threadIdx.x;
    if (e >= N_EDGES) return;
    int d;
    if (g_is64) d = (int)((const long long*)ei_raw)[N_EDGES + e];
    else        d = ((const int*)ei_raw)[N_EDGES + e];
    atomicAdd(&g_cnt[d], 1);
}

// ---------------- scan pass 1: per-1024-block exclusive prefix + block total ---
// (also emits dinv, fused)
__global__ __launch_bounds__(256) void k_scan1() {
    __shared__ int wsum[8];
    int bid = blockIdx.x, tid = threadIdx.x;
    int lane = tid & 31, wid = tid >> 5;
    int base = bid * SCAN_BLK + tid * 4;

    int v[4];
    #pragma unroll
    for (int i = 0; i < 4; i++) {
        int idx = base + i;
        v[i] = (idx < N_NODES) ? g_cnt[idx] : 0;
        if (idx < N_NODES) g_dinv[idx] = rsqrtf((float)v[i] + 1.0f);
    }
    int t1 = v[0] + v[1];
    int t2 = t1 + v[2];
    int tot = t2 + v[3];

    int x = tot;
    #pragma unroll
    for (int o = 1; o < 32; o <<= 1) {
        int y = __shfl_up_sync(0xFFFFFFFFu, x, o);
        if (lane >= o) x += y;
    }
    if (lane == 31) wsum[wid] = x;
    __syncthreads();
    if (wid == 0) {
        int w = (lane < 8) ? wsum[lane] : 0;
        #pragma unroll
        for (int o = 1; o < 8; o <<= 1) {
            int y = __shfl_up_sync(0xFFFFFFFFu, w, o);
            if (lane >= o) w += y;
        }
        if (lane < 8) wsum[lane] = w;
        if (lane == 7) g_bsum[bid] = w;
    }
    __syncthreads();

    int thread_excl = x - tot + (wid > 0 ? wsum[wid - 1] : 0);
    int p[4] = {thread_excl, thread_excl + v[0], thread_excl + t1, thread_excl + t2};
    #pragma unroll
    for (int i = 0; i < 4; i++) {
        int idx = base + i;
        if (idx < N_NODES) g_rowptr[idx] = p[i];
    }
}

// scan pass 2 (fused former scan2+scan3): each 256-wide block redundantly
// reduces the g_bsum prefix for its (single) 1024-block, then finalizes rowptr.
__global__ __launch_bounds__(256) void k_scan3() {
    __shared__ int s_off;
    int base = blockIdx.x * 256;
    int blk = base >> 10;          // all 256 indices share one scan-block id
    if (threadIdx.x < 32) {
        int s = 0;
        for (int j = threadIdx.x; j < blk; j += 32) s += g_bsum[j];
        #pragma unroll
        for (int o = 16; o > 0; o >>= 1) s += __shfl_xor_sync(0xFFFFFFFFu, s, o);
        if (threadIdx.x == 0) s_off = s;
    }
    __syncthreads();
    int i = base + threadIdx.x;
    if (i < N_NODES) {
        int r = g_rowptr[i] + s_off;
        g_rowptr[i] = r;
        g_pos[i] = r;
    }
    if (blockIdx.x == 0 && threadIdx.x == 0) g_rowptr[N_NODES] = N_EDGES;
}

// fill CSR: src index only; 1 edge/thread (max atomic MLP)
__global__ void k_scatter(const void* __restrict__ ei_raw) {
    int e = blockIdx.x * blockDim.x + threadIdx.x;
    if (e >= N_EDGES) return;
    int s, d;
    load_edge(ei_raw, e, s, d);
    int p = atomicAdd(&g_pos[d], 1);
    g_csrc[p] = s;
}

// ---------------- GEMM1 (tf32 mma + cp.async double buffer) -------------------
#define BM 128
#define BK 32
#define A_PAD 36
#define B_PAD 132
#define G1_SMEM ((2 * BM * A_PAD + 2 * BK * B_PAD) * 4)   // 70656 bytes

__device__ __forceinline__ void mma_tf32(float c[4], const unsigned a[4], const unsigned b[2]) {
    asm volatile(
        "mma.sync.aligned.m16n8k8.row.col.f32.tf32.tf32.f32 "
        "{%0,%1,%2,%3}, {%4,%5,%6,%7}, {%8,%9}, {%0,%1,%2,%3};"
        : "+f"(c[0]), "+f"(c[1]), "+f"(c[2]), "+f"(c[3])
        : "r"(a[0]), "r"(a[1]), "r"(a[2]), "r"(a[3]), "r"(b[0]), "r"(b[1]));
}

__global__ __launch_bounds__(256, 2) void k_gemm1_tc(const float* __restrict__ X,
                                                     const float* __restrict__ W) {
    extern __shared__ unsigned dynsmem[];
    unsigned* Asm = dynsmem;                      // [2][BM][A_PAD]
    unsigned* Bsm = dynsmem + 2 * BM * A_PAD;     // [2][BK][B_PAD]
    #define AS(b, m, k) Asm[(b) * BM * A_PAD + (m) * A_PAD + (k)]
    #define BS(b, k, n) Bsm[(b) * BK * B_PAD + (k) * B_PAD + (n)]

    const int tid = threadIdx.x;
    const int wid = tid >> 5;
    const int lane = tid & 31;
    const int g  = lane >> 2;
    const int tg = lane & 3;
    const int wm = wid >> 2;
    const int wn = wid & 3;
    const int mBase = wm * 64;
    const int nBase = wn * 32;
    const int rowBase = blockIdx.x * BM;

    float c[4][4][4];
    #pragma unroll
    for (int mi = 0; mi < 4; mi++)
        #pragma unroll
        for (int ni = 0; ni < 4; ni++)
            #pragma unroll
            for (int r = 0; r < 4; r++) c[mi][ni][r] = 0.0f;

    auto load_tiles = [&](int buf, int k0) {
        #pragma unroll
        for (int i = 0; i < 4; i++) {
            int slot = tid + i * 256;
            int m  = slot >> 3;
            int kq = slot & 7;
            int gr = rowBase + m;
            int valid = (gr < N_NODES);
            const float* src = X + (size_t)(valid ? gr : 0) * N_FEAT + k0 + kq * 4;
            cp16(&AS(buf, m, kq * 4), src, valid ? 16 : 0);
        }
        #pragma unroll
        for (int i = 0; i < 4; i++) {
            int slot = tid + i * 256;
            int kk = slot >> 5;
            int nq = slot & 31;
            cp16(&BS(buf, kk, nq * 4), W + (size_t)(k0 + kk) * HIDDEN + nq * 4, 16);
        }
        cp_commit();
    };

    load_tiles(0, 0);

    const int NIT = N_FEAT / BK;   // 16
    for (int it = 0; it < NIT; it++) {
        int cur = it & 1;
        if (it < NIT - 1) load_tiles(cur ^ 1, (it + 1) * BK);
        if (it < NIT - 1) { asm volatile("cp.async.wait_group 1;" ::: "memory"); }
        else              { asm volatile("cp.async.wait_group 0;" ::: "memory"); }
        __syncthreads();

        #pragma unroll
        for (int ks = 0; ks < 4; ks++) {
            const int kb = ks * 8;
            unsigned a[4][4];
            #pragma unroll
            for (int mi = 0; mi < 4; mi++) {
                int r0 = mBase + mi * 16 + g;
                a[mi][0] = AS(cur, r0,     kb + tg);
                a[mi][1] = AS(cur, r0 + 8, kb + tg);
                a[mi][2] = AS(cur, r0,     kb + tg + 4);
                a[mi][3] = AS(cur, r0 + 8, kb + tg + 4);
            }
            unsigned b[4][2];
            #pragma unroll
            for (int ni = 0; ni < 4; ni++) {
                int col = nBase + ni * 8 + g;
                b[ni][0] = BS(cur, kb + tg,     col);
                b[ni][1] = BS(cur, kb + tg + 4, col);
            }
            #pragma unroll
            for (int mi = 0; mi < 4; mi++)
                #pragma unroll
                for (int ni = 0; ni < 4; ni++)
                    mma_tf32(c[mi][ni], a[mi], b[ni]);
        }
        __syncthreads();
    }

    #pragma unroll
    for (int mi = 0; mi < 4; mi++) {
        int r0 = rowBase + mBase + mi * 16 + g;
        #pragma unroll
        for (int ni = 0; ni < 4; ni++) {
            int colu = (nBase + ni * 8) / 2 + tg;
            if (r0 < N_NODES)
                g_hp[(size_t)r0 * 64 + colu] = pack_bf16(c[mi][ni][0], c[mi][ni][1]);
            if (r0 + 8 < N_NODES)
                g_hp[(size_t)(r0 + 8) * 64 + colu] = pack_bf16(c[mi][ni][2], c[mi][ni][3]);
        }
    }
    #undef AS
    #undef BS
}

// ---------------- agg1: CSR gather, weight = dinv[s]; final *dinv[n] ----------
__global__ __launch_bounds__(256) void k_agg1_g(const float* __restrict__ b1) {
    int t = blockIdx.x * blockDim.x + threadIdx.x;
    int n = t >> 5;
    if (n >= N_NODES) return;
    int lane = t & 31;

    float wn = g_dinv[n];

    uint2 su = *(const uint2*)&g_hp[(size_t)n * 64 + 2 * lane];
    float2 s0 = unpack_bf16(su.x), s1 = unpack_bf16(su.y);
    float4 acc = make_float4(s0.x * wn, s0.y * wn, s1.x * wn, s1.y * wn);

    int e   = g_rowptr[n];
    int end = g_rowptr[n + 1];

    for (; e + 4 <= end; e += 4) {
        int i0 = g_csrc[e], i1 = g_csrc[e + 1], i2 = g_csrc[e + 2], i3 = g_csrc[e + 3];
        float w0 = g_dinv[i0], w1 = g_dinv[i1], w2 = g_dinv[i2], w3 = g_dinv[i3];
        uint2 u0 = *(const uint2*)&g_hp[(size_t)i0 * 64 + 2 * lane];
        uint2 u1 = *(const uint2*)&g_hp[(size_t)i1 * 64 + 2 * lane];
        uint2 u2 = *(const uint2*)&g_hp[(size_t)i2 * 64 + 2 * lane];
        uint2 u3 = *(const uint2*)&g_hp[(size_t)i3 * 64 + 2 * lane];
        float2 a, b;
        a = unpack_bf16(u0.x); b = unpack_bf16(u0.y);
        acc.x = fmaf(a.x, w0, acc.x); acc.y = fmaf(a.y, w0, acc.y);
        acc.z = fmaf(b.x, w0, acc.z); acc.w = fmaf(b.y, w0, acc.w);
        a = unpack_bf16(u1.x); b = unpack_bf16(u1.y);
        acc.x = fmaf(a.x, w1, acc.x); acc.y = fmaf(a.y, w1, acc.y);
        acc.z = fmaf(b.x, w1, acc.z); acc.w = fmaf(b.y, w1, acc.w);
        a = unpack_bf16(u2.x); b = unpack_bf16(u2.y);
        acc.x = fmaf(a.x, w2, acc.x); acc.y = fmaf(a.y, w2, acc.y);
        acc.z = fmaf(b.x, w2, acc.z); acc.w = fmaf(b.y, w2, acc.w);
        a = unpack_bf16(u3.x); b = unpack_bf16(u3.y);
        acc.x = fmaf(a.x, w3, acc.x); acc.y = fmaf(a.y, w3, acc.y);
        acc.z = fmaf(b.x, w3, acc.z); acc.w = fmaf(b.y, w3, acc.w);
    }
    for (; e < end; e++) {
        int i0 = g_csrc[e];
        float w0 = g_dinv[i0];
        uint2 u0 = *(const uint2*)&g_hp[(size_t)i0 * 64 + 2 * lane];
        float2 a = unpack_bf16(u0.x), b = unpack_bf16(u0.y);
        acc.x = fmaf(a.x, w0, acc.x); acc.y = fmaf(a.y, w0, acc.y);
        acc.z = fmaf(b.x, w0, acc.z); acc.w = fmaf(b.y, w0, acc.w);
    }

    float4 bv = *(const float4*)&b1[lane * 4];
    acc.x = fmaxf(fmaf(acc.x, wn, bv.x), 0.0f);
    acc.y = fmaxf(fmaf(acc.y, wn, bv.y), 0.0f);
    acc.z = fmaxf(fmaf(acc.z, wn, bv.z), 0.0f);
    acc.w = fmaxf(fmaf(acc.w, wn, bv.w), 0.0f);

    uint2 o;
    o.x = pack_bf16(acc.x, acc.y);
    o.y = pack_bf16(acc.z, acc.w);
    *(uint2*)&g_a1p[(size_t)n * 64 + 2 * lane] = o;
}

// ---------------- GEMM2 (bf16 mma): g_h2p = dinv * (a1' @ W2) ------------------
#define A2_PAD 68
__global__ __launch_bounds__(256) void k_gemm2_tc(const float* __restrict__ W2) {
    __shared__ unsigned sAp[128][A2_PAD];
    __shared__ unsigned sBp[64][N_CLASS];

    const int tid = threadIdx.x;
    const int wid = tid >> 5;
    const int lane = tid & 31;
    const int g  = lane >> 2;
    const int tg = lane & 3;
    const int rowBase = blockIdx.x * 128;

    for (int i = tid; i < 64 * N_CLASS; i += 256) {
        int k2 = i / N_CLASS, n = i % N_CLASS;
        float lo = W2[(size_t)(2 * k2) * N_CLASS + n];
        float hi = W2[(size_t)(2 * k2 + 1) * N_CLASS + n];
        sBp[k2][n] = pack_bf16(lo, hi);
    }
    #pragma unroll
    for (int i = 0; i < 8; i++) {
        int slot = tid + i * 256;
        int m = slot >> 4;
        int j = slot & 15;
        int gr = rowBase + m;
        int valid = (gr < N_NODES);
        cp16(&sAp[m][j * 4], g_a1p + (size_t)(valid ? gr : 0) * 64 + j * 4, valid ? 16 : 0);
    }
    cp_commit();
    asm volatile("cp.async.wait_group 0;" ::: "memory");
    __syncthreads();

    const int mBase = wid * 16;
    float c[5][4];
    #pragma unroll
    for (int ni = 0; ni < 5; ni++)
        #pragma unroll
        for (int r = 0; r < 4; r++) c[ni][r] = 0.0f;

    #pragma unroll
    for (int ks = 0; ks < 8; ks++) {
        int k2b = ks * 8;
        int r0 = mBase + g;
        unsigned a0 = sAp[r0    ][k2b + tg];
        unsigned a1 = sAp[r0 + 8][k2b + tg];
        unsigned a2 = sAp[r0    ][k2b + tg + 4];
        unsigned a3 = sAp[r0 + 8][k2b + tg + 4];
        #pragma unroll
        for (int ni = 0; ni < 5; ni++) {
            unsigned b0 = sBp[k2b + tg    ][ni * 8 + g];
            unsigned b1r = sBp[k2b + tg + 4][ni * 8 + g];
            asm volatile(
                "mma.sync.aligned.m16n8k16.row.col.f32.bf16.bf16.f32 "
                "{%0,%1,%2,%3}, {%4,%5,%6,%7}, {%8,%9}, {%0,%1,%2,%3};"
                : "+f"(c[ni][0]), "+f"(c[ni][1]), "+f"(c[ni][2]), "+f"(c[ni][3])
                : "r"(a0), "r"(a1), "r"(a2), "r"(a3), "r"(b0), "r"(b1r));
        }
    }

    int r0 = rowBase + mBase + g;
    float w0 = (r0 < N_NODES) ? g_dinv[r0] : 0.0f;
    float w1 = (r0 + 8 < N_NODES) ? g_dinv[r0 + 8] : 0.0f;
    #pragma unroll
    for (int ni = 0; ni < 5; ni++) {
        int colu = ni * 4 + tg;
        if (r0 < N_NODES)
            g_h2p[(size_t)r0 * 20 + colu] = pack_bf16(c[ni][0] * w0, c[ni][1] * w0);
        if (r0 + 8 < N_NODES)
            g_h2p[(size_t)(r0 + 8) * 20 + colu] = pack_bf16(c[ni][2] * w1, c[ni][3] * w1);
    }
}

// ---------------- fused agg2 + log_softmax: warp per node ---------------------
__global__ __launch_bounds__(256) void k_agg2lsm(const float* __restrict__ b2,
                                                 float* __restrict__ out) {
    int n = blockIdx.x * 8 + (threadIdx.x >> 5);
    if (n >= N_NODES) return;
    int lane = threadIdx.x & 31;
    bool active = lane < 20;

    float wn = g_dinv[n];
    float2 acc = make_float2(0.0f, 0.0f);
    if (active) acc = unpack_bf16(g_h2p[(size_t)n * 20 + lane]);

    int e   = g_rowptr[n];
    int end = g_rowptr[n + 1];
    for (; e + 2 <= end; e += 2) {
        int i0 = g_csrc[e], i1 = g_csrc[e + 1];
        if (active) {
            float2 v0 = unpack_bf16(g_h2p[(size_t)i0 * 20 + lane]);
            float2 v1 = unpack_bf16(g_h2p[(size_t)i1 * 20 + lane]);
            acc.x += v0.x + v1.x;
            acc.y += v0.y + v1.y;
        }
    }
    if (e < end) {
        int i0 = g_csrc[e];
        if (active) {
            float2 v0 = unpack_bf16(g_h2p[(size_t)i0 * 20 + lane]);
            acc.x += v0.x;
            acc.y += v0.y;
        }
    }

    float x0 = -1e30f, x1 = -1e30f;
    if (active) {
        float2 bb = *(const float2*)&b2[2 * lane];
        x0 = fmaf(acc.x, wn, bb.x);
        x1 = fmaf(acc.y, wn, bb.y);
    }

    float m = fmaxf(x0, x1);
    #pragma unroll
    for (int o = 16; o > 0; o >>= 1) m = fmaxf(m, __shfl_xor_sync(0xFFFFFFFFu, m, o));

    float s = active ? (expf(x0 - m) + expf(x1 - m)) : 0.0f;
    #pragma unroll
    for (int o = 16; o > 0; o >>= 1) s += __shfl_xor_sync(0xFFFFFFFFu, s, o);

    float ls = m + logf(s);
    if (active)
        *(float2*)&out[(size_t)n * N_CLASS + 2 * lane] = make_float2(x0 - ls, x1 - ls);
}

// ---------------- launcher: fork-join (prep || gemm1) --------------------------
extern "C" void kernel_launch(void* const* d_in, const int* in_sizes, int n_in,
                              void* d_out, int out_size) {
    const float* x  = (const float*)d_in[0];
    const void*  ei = d_in[1];
    const float* W1 = (const float*)d_in[2];
    const float* b1 = (const float*)d_in[3];
    const float* W2 = (const float*)d_in[4];
    const float* b2 = (const float*)d_in[5];
    float* out = (float*)d_out;

    static cudaStream_t s_prep = nullptr;
    static cudaEvent_t ev_fork = nullptr, ev_join = nullptr;
    if (s_prep == nullptr) {
        cudaStreamCreateWithFlags(&s_prep, cudaStreamNonBlocking);
        cudaEventCreateWithFlags(&ev_fork, cudaEventDisableTiming);
        cudaEventCreateWithFlags(&ev_join, cudaEventDisableTiming);
        cudaFuncSetAttribute(k_gemm1_tc, cudaFuncAttributeMaxDynamicSharedMemorySize, G1_SMEM);
    }

    // fork: prep chain on side stream, gemm1 on main stream
    cudaEventRecord(ev_fork, 0);
    cudaStreamWaitEvent(s_prep, ev_fork, 0);

    k_init<<<(N_NODES + 255) / 256, 256, 0, s_prep>>>((const unsigned*)ei);
    k_count<<<(N_EDGES + 255) / 256, 256, 0, s_prep>>>(ei);
    k_scan1<<<SCAN_NBLK, 256, 0, s_prep>>>();
    k_scan3<<<(N_NODES + 255) / 256, 256, 0, s_prep>>>();
    k_scatter<<<(N_EDGES + 255) / 256, 256, 0, s_prep>>>(ei);

    k_gemm1_tc<<<(N_NODES + BM - 1) / BM, 256, G1_SMEM>>>(x, W1);

    // join
    cudaEventRecord(ev_join, s_prep);
    cudaStreamWaitEvent(0, ev_join, 0);

    k_agg1_g<<<(N_NODES * 32 + 255) / 256, 256>>>(b1);
    k_gemm2_tc<<<(N_NODES + 127) / 128, 256>>>(W2);
    k_agg2lsm<<<(N_NODES + 7) / 8, 256>>>(b2, out);
}